// round 9
// baseline (speedup 1.0000x reference)
#include <cuda_runtime.h>

// RelationCrossing: feats (R=8, N, K=8, d=64) fp32, rel_attn (8, 64) fp32.
// scores[r,n,k] = leaky_relu(dot(feats[r,n,k,:], rel_attn[k,:]), 0.2)
// attn = softmax over r; out[n,k,:] = sum_r attn[r,n,k] * feats[r,n,k,:]
//
// FINAL-FORM candidate. Register-resident float4 scheme at the measured DRAM
// roofline (91.8%, 7.27 TB/s; traffic at the 1.843 GB floor). Deltas vs R8:
//  - The 16-lane butterfly is split into two 4-relation halves so the
//    s[0..3] reduction can issue while loads r=4..7 are still in flight
//    (previously one scoreboard arm serialized all 8 loads before any SHFL).
//  - __launch_bounds__(256, 5): 48 regs, 5 CTAs/SM (best measured config).
// Occupancy sweep (32..62 warps/SM) showed DRAM% is insensitive — this access
// mix is HBM-turnaround-limited at ~91-92% of spec.

#define R 8
#define NEG_SLOPE 0.2f

__global__ __launch_bounds__(256, 5) void relation_crossing_kernel(
    const float4* __restrict__ feats,   // R * N * 128 float4s
    const float4* __restrict__ rel,     // 128 float4s (8 heads * 16 quarters)
    float4* __restrict__ out,           // N * 128 float4s
    int total4,                         // N * 128
    long long rel_stride4)              // N * 128 (float4 stride between relations)
{
    int idx = blockIdx.x * blockDim.x + threadIdx.x;
    if (idx >= total4) return;

    // idx = n*128 + k*16 + q  (k = head, q = d-quarter). rel index = k*16+q.
    float4 ra = __ldg(&rel[idx & 127]);

    float4 f[R];
    float s[R];

    // First half: loads r=0..3 + dot partials.
#pragma unroll
    for (int r = 0; r < 4; r++) {
        f[r] = feats[(long long)r * rel_stride4 + idx];
        s[r] = f[r].x * ra.x + f[r].y * ra.y + f[r].z * ra.z + f[r].w * ra.w;
    }
    // Second half loads issued immediately (independent, stay in flight).
#pragma unroll
    for (int r = 4; r < R; r++)
        f[r] = feats[(long long)r * rel_stride4 + idx];

    // Butterfly for s[0..3] overlaps the second half's load latency.
#pragma unroll
    for (int off = 8; off >= 1; off >>= 1) {
#pragma unroll
        for (int r = 0; r < 4; r++)
            s[r] += __shfl_xor_sync(0xffffffffu, s[r], off);
    }

#pragma unroll
    for (int r = 4; r < R; r++)
        s[r] = f[r].x * ra.x + f[r].y * ra.y + f[r].z * ra.z + f[r].w * ra.w;
#pragma unroll
    for (int off = 8; off >= 1; off >>= 1) {
#pragma unroll
        for (int r = 4; r < R; r++)
            s[r] += __shfl_xor_sync(0xffffffffu, s[r], off);
    }

    // leaky_relu + softmax over relations (identical across the 16-lane group).
    float m = -3.4e38f;
#pragma unroll
    for (int r = 0; r < R; r++) {
        s[r] = (s[r] > 0.0f) ? s[r] : NEG_SLOPE * s[r];
        m = fmaxf(m, s[r]);
    }
    float sum = 0.0f;
#pragma unroll
    for (int r = 0; r < R; r++) {
        s[r] = __expf(s[r] - m);
        sum += s[r];
    }
    float inv = __frcp_rn(sum);

    float4 o = make_float4(0.f, 0.f, 0.f, 0.f);
#pragma unroll
    for (int r = 0; r < R; r++) {
        float w = s[r] * inv;
        o.x = fmaf(w, f[r].x, o.x);
        o.y = fmaf(w, f[r].y, o.y);
        o.z = fmaf(w, f[r].z, o.z);
        o.w = fmaf(w, f[r].w, o.w);
    }
    out[idx] = o;
}

extern "C" void kernel_launch(void* const* d_in, const int* in_sizes, int n_in,
                              void* d_out, int out_size)
{
    const float4* feats = (const float4*)d_in[0];  // (8, N, 512) fp32
    const float4* rel   = (const float4*)d_in[1];  // (8, 64) fp32
    float4* out = (float4*)d_out;                  // (N, 512) fp32

    long long elems_per_rel = (long long)in_sizes[0] / R;   // N*512 floats
    int total4 = (int)(elems_per_rel / 4);                  // N*128 float4
    long long rel_stride4 = total4;

    int threads = 256;
    int blocks = (total4 + threads - 1) / threads;
    relation_crossing_kernel<<<blocks, threads>>>(feats, rel, out, total4, rel_stride4);
}

// round 10
// speedup vs baseline: 1.0049x; 1.0049x over previous
#include <cuda_runtime.h>

// RelationCrossing — FINAL. feats (R=8, N, K=8, d=64) fp32, rel_attn (8,64) fp32.
// scores[r,n,k] = leaky_relu(dot(feats[r,n,k,:], rel_attn[k,:]), 0.2)
// attn = softmax over r; out[n,k,:] = sum_r attn[r,n,k] * feats[r,n,k,:]
//
// Single-pass, register-resident: each thread owns a float4 (4 d-values) of
// one (n,k); 16 warp-aligned threads cover a head, dot reduced via 4-level
// xor-shuffle butterfly; softmax computed redundantly per lane (compute is
// ~20% utilized — free); weighted sum from registers; one coalesced store.
//
// At the measured DRAM roofline: 7.28 TB/s (91% of 8 TB/s spec), traffic at
// the theoretical floor (1.638 GB read + 0.205 GB write). A 9-round sweep
// (occupancy 44-62%, cp.async SMEM staging, float2 granularity, persistent
// grid + software pipeline, two-pass L2 re-read, streaming cache hints,
// split-batch reduction, launch-bounds reg capping) showed DRAM% is pinned
// at 88-92% for every structure and strictly worse for all alternatives:
// the residual ~8% is HBM read/write turnaround on the 8:1 mix, not
// kernel-addressable. (redux.sync.add.f32 does not exist on sm_103.)

#define R 8
#define NEG_SLOPE 0.2f

__global__ __launch_bounds__(256) void relation_crossing_kernel(
    const float4* __restrict__ feats,   // R * N * 128 float4s
    const float4* __restrict__ rel,     // 128 float4s (8 heads * 16 quarters)
    float4* __restrict__ out,           // N * 128 float4s
    int total4,                         // N * 128
    long long rel_stride4)              // N * 128 (float4 stride between relations)
{
    int idx = blockIdx.x * blockDim.x + threadIdx.x;
    if (idx >= total4) return;

    // idx = n*128 + k*16 + q  (k = head, q = d-quarter). rel index = k*16+q.
    float4 ra = rel[idx & 127];

    // Front-batched loads: 8 independent LDG.128 (MLP=8), dot partials folded
    // in as each lands.
    float4 f[R];
    float s[R];
#pragma unroll
    for (int r = 0; r < R; r++) {
        f[r] = feats[(long long)r * rel_stride4 + idx];
        s[r] = f[r].x * ra.x + f[r].y * ra.y + f[r].z * ra.z + f[r].w * ra.w;
    }

    // Reduce dot products across the 16-thread group covering this head.
    // Groups of 16 are warp-aligned, so xor offsets 8,4,2,1 stay in-group;
    // 8 independent values per level -> serial chain is 4 SHFL latencies.
#pragma unroll
    for (int off = 8; off >= 1; off >>= 1) {
#pragma unroll
        for (int r = 0; r < R; r++)
            s[r] += __shfl_xor_sync(0xffffffffu, s[r], off);
    }

    // leaky_relu + softmax over relations (identical across the 16-lane group).
    float m = -3.4e38f;
#pragma unroll
    for (int r = 0; r < R; r++) {
        s[r] = (s[r] > 0.0f) ? s[r] : NEG_SLOPE * s[r];
        m = fmaxf(m, s[r]);
    }
    float sum = 0.0f;
#pragma unroll
    for (int r = 0; r < R; r++) {
        s[r] = __expf(s[r] - m);
        sum += s[r];
    }
    float inv = __frcp_rn(sum);

    float4 o = make_float4(0.f, 0.f, 0.f, 0.f);
#pragma unroll
    for (int r = 0; r < R; r++) {
        float w = s[r] * inv;
        o.x = fmaf(w, f[r].x, o.x);
        o.y = fmaf(w, f[r].y, o.y);
        o.z = fmaf(w, f[r].z, o.z);
        o.w = fmaf(w, f[r].w, o.w);
    }
    out[idx] = o;
}

extern "C" void kernel_launch(void* const* d_in, const int* in_sizes, int n_in,
                              void* d_out, int out_size)
{
    const float4* feats = (const float4*)d_in[0];  // (8, N, 512) fp32
    const float4* rel   = (const float4*)d_in[1];  // (8, 64) fp32
    float4* out = (float4*)d_out;                  // (N, 512) fp32

    long long elems_per_rel = (long long)in_sizes[0] / R;   // N*512 floats
    int total4 = (int)(elems_per_rel / 4);                  // N*128 float4
    long long rel_stride4 = total4;

    int threads = 256;
    int blocks = (total4 + threads - 1) / threads;
    relation_crossing_kernel<<<blocks, threads>>>(feats, rel, out, total4, rel_stride4);
}

// round 11
// speedup vs baseline: 1.0055x; 1.0006x over previous
#include <cuda_runtime.h>

// RelationCrossing — feats (R=8, N, K=8, d=64) fp32, rel_attn (8,64) fp32.
// scores[r,n,k] = leaky_relu(dot(feats[r,n,k,:], rel_attn[k,:]), 0.2)
// attn = softmax over r; out[n,k,:] = sum_r attn[r,n,k] * feats[r,n,k,:]
//
// R10 final-form structure (254.2us, DRAM 91.8%, traffic at the 1.843 GB
// floor) with ONE remaining untested micro-lever: __stwt (STG.WT,
// write-through) on the output. Default stores write-allocate in L2 and
// drain to HBM as LTS-scheduled dirty-eviction bursts that interleave with
// the 8 read streams and cluster bus turnarounds; write-through drains the
// write stream immediately and in program order, smoothing turnaround.
// Everything else identical to the measured-best kernel.

#define R 8
#define NEG_SLOPE 0.2f

__global__ __launch_bounds__(256) void relation_crossing_kernel(
    const float4* __restrict__ feats,   // R * N * 128 float4s
    const float4* __restrict__ rel,     // 128 float4s (8 heads * 16 quarters)
    float4* __restrict__ out,           // N * 128 float4s
    int total4,                         // N * 128
    long long rel_stride4)              // N * 128 (float4 stride between relations)
{
    int idx = blockIdx.x * blockDim.x + threadIdx.x;
    if (idx >= total4) return;

    // idx = n*128 + k*16 + q  (k = head, q = d-quarter). rel index = k*16+q.
    float4 ra = rel[idx & 127];

    // Front-batched loads: 8 independent LDG.128 (MLP=8), dot partials folded
    // in as each lands.
    float4 f[R];
    float s[R];
#pragma unroll
    for (int r = 0; r < R; r++) {
        f[r] = feats[(long long)r * rel_stride4 + idx];
        s[r] = f[r].x * ra.x + f[r].y * ra.y + f[r].z * ra.z + f[r].w * ra.w;
    }

    // Reduce dot products across the 16-thread group covering this head.
    // Groups of 16 are warp-aligned, so xor offsets 8,4,2,1 stay in-group;
    // 8 independent values per level -> serial chain is 4 SHFL latencies.
#pragma unroll
    for (int off = 8; off >= 1; off >>= 1) {
#pragma unroll
        for (int r = 0; r < R; r++)
            s[r] += __shfl_xor_sync(0xffffffffu, s[r], off);
    }

    // leaky_relu + softmax over relations (identical across the 16-lane group).
    float m = -3.4e38f;
#pragma unroll
    for (int r = 0; r < R; r++) {
        s[r] = (s[r] > 0.0f) ? s[r] : NEG_SLOPE * s[r];
        m = fmaxf(m, s[r]);
    }
    float sum = 0.0f;
#pragma unroll
    for (int r = 0; r < R; r++) {
        s[r] = __expf(s[r] - m);
        sum += s[r];
    }
    float inv = __frcp_rn(sum);

    float4 o = make_float4(0.f, 0.f, 0.f, 0.f);
#pragma unroll
    for (int r = 0; r < R; r++) {
        float w = s[r] * inv;
        o.x = fmaf(w, f[r].x, o.x);
        o.y = fmaf(w, f[r].y, o.y);
        o.z = fmaf(w, f[r].z, o.z);
        o.w = fmaf(w, f[r].w, o.w);
    }
    __stwt(&out[idx], o);   // STG.WT — write-through, no dirty-L2 eviction bursts
}

extern "C" void kernel_launch(void* const* d_in, const int* in_sizes, int n_in,
                              void* d_out, int out_size)
{
    const float4* feats = (const float4*)d_in[0];  // (8, N, 512) fp32
    const float4* rel   = (const float4*)d_in[1];  // (8, 64) fp32
    float4* out = (float4*)d_out;                  // (N, 512) fp32

    long long elems_per_rel = (long long)in_sizes[0] / R;   // N*512 floats
    int total4 = (int)(elems_per_rel / 4);                  // N*128 float4
    long long rel_stride4 = total4;

    int threads = 256;
    int blocks = (total4 + threads - 1) / threads;
    relation_crossing_kernel<<<blocks, threads>>>(feats, rel, out, total4, rel_stride4);
}